// round 1
// baseline (speedup 1.0000x reference)
#include <cuda_runtime.h>
#include <cstdint>

// Problem constants
#define B_   32
#define C_   128
#define HW_  56
#define F_   128
#define PIX_ (HW_*HW_)   // 3136

// SMEM layout strides (floats)
#define XS_CSTRIDE 248   // per-channel stride: 4 h rows * 62
#define XS_HSTRIDE 62    // padded row of 60 (w = -1..58) -> 62 for bank-conflict-free A reads
#define WS_KSTRIDE 136   // 128 filters padded to 136 for conflict-free B reads

__device__ __forceinline__ void mma_tf32(float d[4], const uint32_t a[4], const uint32_t b[2]) {
    asm volatile(
        "mma.sync.aligned.m16n8k8.row.col.f32.tf32.tf32.f32 "
        "{%0,%1,%2,%3}, {%4,%5,%6,%7}, {%8,%9}, {%0,%1,%2,%3};\n"
        : "+f"(d[0]), "+f"(d[1]), "+f"(d[2]), "+f"(d[3])
        : "r"(a[0]), "r"(a[1]), "r"(a[2]), "r"(a[3]),
          "r"(b[0]), "r"(b[1]));
}

__global__ __launch_bounds__(256)
void spiking_conv2d_tf32_kernel(const float* __restrict__ x,   // [32,128,56,56]
                                const float* __restrict__ Wg,  // [1152,128]  row = c*9 + kh*3 + kw
                                const float* __restrict__ Di,  // [9,128] (row 0 used)
                                float* __restrict__ out)       // [32,56,56,128]
{
    __shared__ float xs[32 * XS_CSTRIDE];  // 31744 B : [c(32)][hl(4)][wi(62, 60 used)]
    __shared__ float ws[32 * WS_KSTRIDE];  // 17408 B : [k(32)][f(136, 128 used)]
    // total static smem = 49152 B = 48 KB exactly

    const int tid   = threadIdx.x;
    const int lane  = tid & 31;
    const int warp  = tid >> 5;
    const int warpM = warp >> 2;   // 0..1  -> 64 pixel rows each
    const int warpN = warp & 3;    // 0..3  -> 32 filters each
    const int b     = blockIdx.y;
    const int h0    = blockIdx.x * 2;   // this tile covers output rows h0, h0+1 (112 pixels + 16 pad)

    // ---- per-thread A-row geometry (8 row positions: 4 m-tiles x {0,+8}) ----
    int offm[8];
    #pragma unroll
    for (int i = 0; i < 8; i++) {
        int mt = i >> 1, half = i & 1;
        int m = warpM * 64 + mt * 16 + half * 8 + (lane >> 2);
        int hh = 0, w = 0;
        if (m < 112) { hh = m / HW_; w = m % HW_; }   // pad rows read (0,0): harmless garbage
        offm[i] = hh * XS_HSTRIDE + w;                // add dh*62 + dw at use (wi = w + dw since row stores w=-1 at 0)
    }

    // ---- per-thread threshold values (epilogue) ----
    float thr[4][2];
    #pragma unroll
    for (int nt = 0; nt < 4; nt++) {
        int f = warpN * 32 + nt * 8 + 2 * (lane & 3);
        thr[nt][0] = 1.0f - Di[f];
        thr[nt][1] = 1.0f - Di[f + 1];
    }

    float acc[4][4][4];
    #pragma unroll
    for (int mt = 0; mt < 4; mt++)
        #pragma unroll
        for (int nt = 0; nt < 4; nt++)
            #pragma unroll
            for (int r = 0; r < 4; r++) acc[mt][nt][r] = 0.0f;

    // ---- weight tile register prefetch: 16 floats/thread (4 x float4) ----
    float4 wv0, wv1, wv2, wv3;
    const int wk = tid >> 3;            // k row 0..31
    const int wf = (tid & 7) * 16;      // f start
    auto ldg_ws = [&](int s) {
        int cc = s / 9, off = s - cc * 9;
        const float4* src = (const float4*)(Wg + (size_t)((cc * 32 + wk) * 9 + off) * F_ + wf);
        wv0 = src[0]; wv1 = src[1]; wv2 = src[2]; wv3 = src[3];
    };
    auto sts_ws = [&]() {
        float4* dst = (float4*)(ws + wk * WS_KSTRIDE + wf);
        dst[0] = wv0; dst[1] = wv1; dst[2] = wv2; dst[3] = wv3;
    };

    // ---- input region load for channel chunk cc: [32c][4h][60w], zero-padded ----
    auto load_xs = [&](int cc) {
        const float* xb = x + ((size_t)b * C_ + cc * 32) * PIX_;
        for (int idx = tid; idx < 32 * 4 * 60; idx += 256) {
            int c   = idx / 240;
            int rem = idx - c * 240;
            int hl  = rem / 60;
            int wi  = rem - hl * 60;
            int h   = h0 - 1 + hl;
            int w   = wi - 1;
            float v = 0.0f;
            if ((unsigned)h < (unsigned)HW_ && (unsigned)w < (unsigned)HW_)
                v = xb[c * PIX_ + h * HW_ + w];
            xs[c * XS_CSTRIDE + hl * XS_HSTRIDE + wi] = v;
        }
    };

    // ---- prologue ----
    ldg_ws(0);
    load_xs(0);
    sts_ws();
    __syncthreads();

    // ---- main K loop: 36 steps = 4 c-chunks x 9 taps, each step K=32 (4 MMAs of K=8) ----
    const int colA = lane & 3;
    for (int s = 0; s < 36; s++) {
        int cc  = s / 9;
        int off = s - cc * 9;
        int dh  = off / 3;
        int dw  = off - dh * 3;
        int doff = dh * XS_HSTRIDE + dw;

        if (s < 35) ldg_ws(s + 1);   // prefetch next weight tile into regs (overlaps compute)

        #pragma unroll
        for (int kk = 0; kk < 4; kk++) {
            const int k0 = kk * 8;
            // A fragments (4 m-tiles)
            uint32_t a[4][4];
            #pragma unroll
            for (int mt = 0; mt < 4; mt++) {
                const float* b0 = xs + offm[mt * 2 + 0] + doff;
                const float* b1 = xs + offm[mt * 2 + 1] + doff;
                a[mt][0] = __float_as_uint(b0[(k0 + colA)     * XS_CSTRIDE]);
                a[mt][1] = __float_as_uint(b1[(k0 + colA)     * XS_CSTRIDE]);
                a[mt][2] = __float_as_uint(b0[(k0 + colA + 4) * XS_CSTRIDE]);
                a[mt][3] = __float_as_uint(b1[(k0 + colA + 4) * XS_CSTRIDE]);
            }
            // B fragments (4 n-tiles)
            uint32_t bf[4][2];
            #pragma unroll
            for (int nt = 0; nt < 4; nt++) {
                int f = warpN * 32 + nt * 8 + (lane >> 2);
                bf[nt][0] = __float_as_uint(ws[(k0 + (lane & 3))     * WS_KSTRIDE + f]);
                bf[nt][1] = __float_as_uint(ws[(k0 + (lane & 3) + 4) * WS_KSTRIDE + f]);
            }
            #pragma unroll
            for (int mt = 0; mt < 4; mt++)
                #pragma unroll
                for (int nt = 0; nt < 4; nt++)
                    mma_tf32(acc[mt][nt], a[mt], bf[nt]);
        }

        __syncthreads();                         // compute(s) done everywhere
        if (s < 35) sts_ws();                    // safe: ws no longer being read
        if (off == 8 && s < 35) load_xs(cc + 1); // next channel chunk (xs no longer read)
        __syncthreads();                         // new ws / xs visible
    }

    // ---- epilogue: ti = min(y + 1 - Di[f], 1), NHWC store ----
    #pragma unroll
    for (int mt = 0; mt < 4; mt++) {
        #pragma unroll
        for (int half = 0; half < 2; half++) {
            int m = warpM * 64 + mt * 16 + half * 8 + (lane >> 2);
            if (m < 112) {
                int hh = m / HW_, w = m % HW_;
                int h  = h0 + hh;
                float* op = out + (((size_t)b * HW_ + h) * HW_ + w) * F_;
                #pragma unroll
                for (int nt = 0; nt < 4; nt++) {
                    int f = warpN * 32 + nt * 8 + 2 * (lane & 3);
                    float v0 = fminf(acc[mt][nt][2 * half + 0] + thr[nt][0], 1.0f);
                    float v1 = fminf(acc[mt][nt][2 * half + 1] + thr[nt][1], 1.0f);
                    float2 vv; vv.x = v0; vv.y = v1;
                    *(float2*)(op + f) = vv;
                }
            }
        }
    }
}

extern "C" void kernel_launch(void* const* d_in, const int* in_sizes, int n_in,
                              void* d_out, int out_size) {
    (void)in_sizes; (void)n_in; (void)out_size;
    const float* x  = (const float*)d_in[0];   // tj  [32,128,56,56]
    const float* Wg = (const float*)d_in[1];   // W   [1152,128]
    const float* Di = (const float*)d_in[2];   // D_i [9,128]
    float* out = (float*)d_out;                // [32,56,56,128]

    dim3 grid(28, 32);   // 28 h-tiles (2 rows each) x 32 batches
    spiking_conv2d_tf32_kernel<<<grid, 256>>>(x, Wg, Di, out);
}

// round 4
// speedup vs baseline: 1.7052x; 1.7052x over previous
#include <cuda_runtime.h>
#include <cstdint>

#define HW_   56
#define C_    128
#define F_    128
#define B_    32
#define PIX_  (HW_*HW_)
#define XHW   58                 // padded spatial
#define STAGE 32768              // A 16KB + B 16KB
#define NST   3
#define DYN   (NST*STAGE + 1024)

// device scratch (static globals = allowed)
__device__ float g_xh[(size_t)B_ * XHW * XHW * C_];  // [b][hp][wp][cperm]
__device__ float g_wt[9 * 4 * 128 * 32];             // [tap][cc][f][kperm]

__device__ __forceinline__ uint32_t smem_u32(const void* p) {
    uint32_t a;
    asm("{ .reg .u64 t; cvta.to.shared.u64 t, %1; cvt.u32.u64 %0, t; }" : "=r"(a) : "l"(p));
    return a;
}
__device__ __forceinline__ void mma_tf32(float d[4], const uint32_t a[4], const uint32_t b[2]) {
    asm volatile(
        "mma.sync.aligned.m16n8k8.row.col.f32.tf32.tf32.f32 "
        "{%0,%1,%2,%3}, {%4,%5,%6,%7}, {%8,%9}, {%0,%1,%2,%3};\n"
        : "+f"(d[0]), "+f"(d[1]), "+f"(d[2]), "+f"(d[3])
        : "r"(a[0]), "r"(a[1]), "r"(a[2]), "r"(a[3]), "r"(b[0]), "r"(b[1]));
}
#define CP_CG(d, s) asm volatile("cp.async.cg.shared.global [%0], [%1], 16;" :: "r"(d), "l"(s))
#define CP_CA(d, s) asm volatile("cp.async.ca.shared.global [%0], [%1], 16;" :: "r"(d), "l"(s))
#define CP_COMMIT() asm volatile("cp.async.commit_group;" ::: "memory")
#define LDS64(r0, r1, a) asm volatile("ld.shared.v2.b32 {%0,%1}, [%2];" : "=r"(r0), "=r"(r1) : "r"(a))

// channel pair-permute within 8-block: c8<4 -> 2*c8 ; else 2*(c8-4)+1
__device__ __host__ __forceinline__ int permC(int c) {
    return (c & ~7) | ((c & 3) << 1) | ((c >> 2) & 1);
}

// ---------- prologue 1: x NCHW -> zero-padded NHWC (channel-permuted) ----------
__global__ __launch_bounds__(256) void k_transpose_x(const float* __restrict__ x) {
    __shared__ float s[HW_ * 130];
    const int hp = blockIdx.x, b = blockIdx.y, tid = threadIdx.x;
    float* dst = g_xh + ((size_t)(b * XHW + hp) * XHW) * C_;
    if (hp == 0 || hp == XHW - 1) {
        for (int i = tid; i < XHW * C_; i += 256) dst[i] = 0.0f;
        return;
    }
    const float* src = x + ((size_t)b * C_) * PIX_ + (hp - 1) * HW_;
    for (int i = tid; i < C_ * HW_; i += 256) {
        int c = i / HW_, w = i - c * HW_;
        s[w * 130 + c] = src[(size_t)c * PIX_ + w];
    }
    __syncthreads();
    for (int o = tid; o < XHW * C_; o += 256) {
        int wp = o >> 7, c = o & 127;
        float v = (wp == 0 || wp == XHW - 1) ? 0.0f : s[(wp - 1) * 130 + c];
        dst[wp * 128 + permC(c)] = v;
    }
}

// ---------- prologue 2: W[(c*9+tap)][f] -> g_wt[tap][cc][f][kperm] ----------
__global__ __launch_bounds__(256) void k_transpose_w(const float* __restrict__ Wg) {
    int i = blockIdx.x * 256 + threadIdx.x;
    if (i < 9 * 4 * 128 * 32) {
        int t  = i / 16384;
        int r  = i - t * 16384;
        int cc = r >> 12;
        int r2 = r & 4095;
        int n  = r2 >> 5;
        int j  = r2 & 31;
        int c  = cc * 32 + ((j >> 3) << 3) + ((j >> 1) & 3) + ((j & 1) << 2);
        g_wt[i] = Wg[(c * 9 + t) * F_ + n];
    }
}

// ---------- main: cp.async-pipelined tf32 mma.sync implicit GEMM ----------
__global__ __launch_bounds__(256, 2)
void k_conv_main(const float* __restrict__ Di, float* __restrict__ out) {
    extern __shared__ float dynsmem[];
    uint32_t dbase = smem_u32(dynsmem);
    dbase = (dbase + 1023u) & ~1023u;

    const int tid   = threadIdx.x;
    const int lane  = tid & 31;
    const int warp  = tid >> 5;
    const int warpM = warp >> 2;   // 0..1
    const int warpN = warp & 3;    // 0..3
    const int b     = blockIdx.y;
    const int h0    = blockIdx.x * 2;

    // epilogue thresholds
    float thr[4][2];
    #pragma unroll
    for (int nt = 0; nt < 4; nt++) {
        int f = warpN * 32 + nt * 8 + 2 * (lane & 3);
        thr[nt][0] = 1.0f - Di[f];
        thr[nt][1] = 1.0f - Di[f + 1];
    }

    float acc[4][4][4];
    #pragma unroll
    for (int mt = 0; mt < 4; mt++)
        #pragma unroll
        for (int nt = 0; nt < 4; nt++)
            #pragma unroll
            for (int r = 0; r < 4; r++) acc[mt][nt][r] = 0.0f;

    // ---- cp.async tables: 4 A-copies + 4 B-copies of 16B per thread ----
    int srcA[4]; uint32_t dstA[4];
    #pragma unroll
    for (int i = 0; i < 4; i++) {
        int idx = tid + 256 * i;        // 0..1023
        int m = idx >> 3, g = idx & 7;
        int meff = (m < 112) ? m : 0;   // dead rows source row 0 (valid mem)
        int hh = (meff >= HW_), w = meff - hh * HW_;
        srcA[i] = (((b * XHW) + h0 + hh) * XHW + w) * 512 + g * 16;
        dstA[i] = m * 128 + ((g ^ (m & 7)) << 4);
    }
    int srcB[4]; uint32_t dstB[4];
    #pragma unroll
    for (int i = 0; i < 4; i++) {
        int idx = tid + 256 * i;
        int n = idx >> 3, g = idx & 7;
        srcB[i] = n * 128 + g * 16;
        dstB[i] = 16384 + n * 128 + ((g ^ (n & 7)) << 4);
    }
    const char* xh = (const char*)g_xh;
    const char* wt = (const char*)g_wt;

    // ---- fragment geometry (swizzled, LDS.64) ----
    const int cA = lane & 3;
    const int x2 = 2 * ((lane >> 2) & 7);
    int okk[4];
    #pragma unroll
    for (int kk = 0; kk < 4; kk++) okk[kk] = ((kk * 4 + cA) ^ x2) << 3;
    uint32_t ab[4][2], bb[4];
    #pragma unroll
    for (int mt = 0; mt < 4; mt++) {
        int r0 = warpM * 64 + mt * 16 + (lane >> 2);
        ab[mt][0] = r0 * 128;
        ab[mt][1] = (r0 + 8) * 128;
    }
    #pragma unroll
    for (int nt = 0; nt < 4; nt++) {
        int n = warpN * 32 + nt * 8 + (lane >> 2);
        bb[nt] = 16384 + n * 128;
    }

    auto issue = [&](int s) {
        int tap = s >> 2, cc = s & 3;
        int dh = tap / 3, dw = tap - dh * 3;
        uint32_t sb = dbase + (s % NST) * STAGE;
        int aadd = (dh * XHW + dw) * 512 + cc * 128;
        int badd = s * 16384;
        #pragma unroll
        for (int i = 0; i < 4; i++) CP_CG(sb + dstA[i], xh + srcA[i] + aadd);
        #pragma unroll
        for (int i = 0; i < 4; i++) CP_CA(sb + dstB[i], wt + srcB[i] + badd);
        CP_COMMIT();
    };

    issue(0);
    for (int s = 0; s < 36; s++) {
        if (s < 35) {
            issue(s + 1);
            asm volatile("cp.async.wait_group 1;" ::: "memory");
        } else {
            asm volatile("cp.async.wait_group 0;" ::: "memory");
        }
        __syncthreads();
        uint32_t sb = dbase + (s % NST) * STAGE;
        #pragma unroll
        for (int kk = 0; kk < 4; kk++) {
            const int o = okk[kk];
            uint32_t a[4][4];
            #pragma unroll
            for (int mt = 0; mt < 4; mt++) {
                LDS64(a[mt][0], a[mt][2], sb + ab[mt][0] + o);  // a0=A[r][c], a2=A[r][c+4]
                LDS64(a[mt][1], a[mt][3], sb + ab[mt][1] + o);  // a1=A[r+8][c], a3=A[r+8][c+4]
            }
            uint32_t bf[4][2];
            #pragma unroll
            for (int nt = 0; nt < 4; nt++)
                LDS64(bf[nt][0], bf[nt][1], sb + bb[nt] + o);   // b0=B[c][n], b1=B[c+4][n]
            #pragma unroll
            for (int mt = 0; mt < 4; mt++)
                #pragma unroll
                for (int nt = 0; nt < 4; nt++)
                    mma_tf32(acc[mt][nt], a[mt], bf[nt]);
        }
    }

    // ---- epilogue: ti = min(y + 1 - Di[f], 1), NHWC float2 stores ----
    #pragma unroll
    for (int mt = 0; mt < 4; mt++) {
        #pragma unroll
        for (int half = 0; half < 2; half++) {
            int m = warpM * 64 + mt * 16 + half * 8 + (lane >> 2);
            if (m < 112) {
                int hh = m / HW_, w = m % HW_;
                int h  = h0 + hh;
                float* op = out + (((size_t)b * HW_ + h) * HW_ + w) * F_;
                #pragma unroll
                for (int nt = 0; nt < 4; nt++) {
                    int f = warpN * 32 + nt * 8 + 2 * (lane & 3);
                    float2 vv;
                    vv.x = fminf(acc[mt][nt][2 * half + 0] + thr[nt][0], 1.0f);
                    vv.y = fminf(acc[mt][nt][2 * half + 1] + thr[nt][1], 1.0f);
                    *(float2*)(op + f) = vv;
                }
            }
        }
    }
}

extern "C" void kernel_launch(void* const* d_in, const int* in_sizes, int n_in,
                              void* d_out, int out_size) {
    (void)in_sizes; (void)n_in; (void)out_size;
    const float* x  = (const float*)d_in[0];   // tj  [32,128,56,56]
    const float* Wg = (const float*)d_in[1];   // W   [1152,128]
    const float* Di = (const float*)d_in[2];   // D_i [9,128]
    float* out = (float*)d_out;

    cudaFuncSetAttribute(k_conv_main, cudaFuncAttributeMaxDynamicSharedMemorySize, DYN);

    dim3 gx(XHW, B_);
    k_transpose_x<<<gx, 256>>>(x);
    k_transpose_w<<<(9 * 4 * 128 * 32 + 255) / 256, 256>>>(Wg);

    dim3 gm(28, B_);   // 28 h-tiles (2 rows) x 32 batches
    k_conv_main<<<gm, 256, DYN>>>(Di, out);
}

// round 5
// speedup vs baseline: 1.8667x; 1.0947x over previous
#include <cuda_runtime.h>
#include <cstdint>

#define HW_   56
#define C_    128
#define F_    128
#define B_    32
#define PIX_  (HW_*HW_)
#define XHW   58                 // padded spatial
#define STAGE 32768              // A 16KB + B 16KB
#define NST   3
#define DYN   (NST*STAGE + 1024)

// device scratch (static globals = allowed)
__device__ float g_xh[(size_t)B_ * XHW * XHW * C_];  // [b][hp][wp][cperm]
__device__ float g_wt[9 * 4 * 128 * 32];             // [tap][cc][f][kperm]

__device__ __forceinline__ uint32_t smem_u32(const void* p) {
    uint32_t a;
    asm("{ .reg .u64 t; cvta.to.shared.u64 t, %1; cvt.u32.u64 %0, t; }" : "=r"(a) : "l"(p));
    return a;
}
__device__ __forceinline__ void mma_tf32(float d[4], const uint32_t a[4], const uint32_t b[2]) {
    asm volatile(
        "mma.sync.aligned.m16n8k8.row.col.f32.tf32.tf32.f32 "
        "{%0,%1,%2,%3}, {%4,%5,%6,%7}, {%8,%9}, {%0,%1,%2,%3};\n"
        : "+f"(d[0]), "+f"(d[1]), "+f"(d[2]), "+f"(d[3])
        : "r"(a[0]), "r"(a[1]), "r"(a[2]), "r"(a[3]), "r"(b[0]), "r"(b[1]));
}
#define CP_CG(d, s) asm volatile("cp.async.cg.shared.global [%0], [%1], 16;" :: "r"(d), "l"(s))
#define CP_CA(d, s) asm volatile("cp.async.ca.shared.global [%0], [%1], 16;" :: "r"(d), "l"(s))
#define CP_COMMIT() asm volatile("cp.async.commit_group;" ::: "memory")
#define LDS64(r0, r1, a) asm volatile("ld.shared.v2.b32 {%0,%1}, [%2];" : "=r"(r0), "=r"(r1) : "r"(a))

// channel pair-permute within 8-block: maps k-pairs so LDS.64 is conflict-free
__device__ __host__ __forceinline__ int permC(int c) {
    return (c & ~7) | ((c & 3) << 1) | ((c >> 2) & 1);
}

// ---------- prologue 1: x NCHW -> zero-padded NHWC (channel-permuted) ----------
__global__ __launch_bounds__(256) void k_transpose_x(const float* __restrict__ x) {
    __shared__ float s[HW_ * 130];
    const int hp = blockIdx.x, bb = blockIdx.y, tid = threadIdx.x;
    float* dst = g_xh + ((size_t)(bb * XHW + hp) * XHW) * C_;
    if (hp == 0 || hp == XHW - 1) {
        for (int i = tid; i < XHW * C_; i += 256) dst[i] = 0.0f;
        return;
    }
    const float* src = x + ((size_t)bb * C_) * PIX_ + (hp - 1) * HW_;
    for (int i = tid; i < C_ * HW_; i += 256) {
        int c = i / HW_, w = i - c * HW_;
        s[w * 130 + c] = src[(size_t)c * PIX_ + w];
    }
    __syncthreads();
    for (int o = tid; o < XHW * C_; o += 256) {
        int wp = o >> 7, c = o & 127;
        float v = (wp == 0 || wp == XHW - 1) ? 0.0f : s[(wp - 1) * 130 + c];
        dst[wp * 128 + permC(c)] = v;
    }
}

// ---------- prologue 2: W[(c*9+tap)][f] -> g_wt[tap][cc][f][kperm] ----------
__global__ __launch_bounds__(256) void k_transpose_w(const float* __restrict__ Wg) {
    int i = blockIdx.x * 256 + threadIdx.x;
    if (i < 9 * 4 * 128 * 32) {
        int t  = i / 16384;
        int r  = i - t * 16384;
        int cc = r >> 12;
        int r2 = r & 4095;
        int n  = r2 >> 5;
        int j  = r2 & 31;
        int c  = cc * 32 + ((j >> 3) << 3) + ((j >> 1) & 3) + ((j & 1) << 2);
        g_wt[i] = Wg[(c * 9 + t) * F_ + n];
    }
}

// ---------- main: flattened-M, depth-2 cp.async pipelined tf32 mma.sync ----------
__global__ __launch_bounds__(256, 2)
void k_conv_main(const float* __restrict__ Di, float* __restrict__ out) {
    extern __shared__ float dynsmem[];
    uint32_t dbase = smem_u32(dynsmem);
    dbase = (dbase + 1023u) & ~1023u;

    const int tid   = threadIdx.x;
    const int lane  = tid & 31;
    const int warp  = tid >> 5;
    const int warpM = warp >> 2;   // 0..1
    const int warpN = warp & 3;    // 0..3
    const int T     = blockIdx.x;  // flattened pixel tile: pixels [T*128, T*128+128)

    // epilogue thresholds
    float thr[4][2];
    #pragma unroll
    for (int nt = 0; nt < 4; nt++) {
        int f = warpN * 32 + nt * 8 + 2 * (lane & 3);
        thr[nt][0] = 1.0f - Di[f];
        thr[nt][1] = 1.0f - Di[f + 1];
    }

    float acc[4][4][4];
    #pragma unroll
    for (int mt = 0; mt < 4; mt++)
        #pragma unroll
        for (int nt = 0; nt < 4; nt++)
            #pragma unroll
            for (int r = 0; r < 4; r++) acc[mt][nt][r] = 0.0f;

    // ---- cp.async tables: 4 A-copies + 4 B-copies of 16B per thread ----
    int srcA[4]; uint32_t dstA[4];
    #pragma unroll
    for (int i = 0; i < 4; i++) {
        int idx = tid + 256 * i;        // 0..1023
        int m = idx >> 3, g = idx & 7;
        int p = T * 128 + m;            // global pixel (always valid: 784*128 = 100352)
        int bb = p / PIX_;
        int r  = p - bb * PIX_;
        int h  = r / HW_;
        int w  = r - h * HW_;
        srcA[i] = ((bb * XHW + h) * XHW + w) * 512 + g * 16;   // base (dh=dw=0)
        dstA[i] = m * 128 + ((g ^ (m & 7)) << 4);
    }
    int srcB[4]; uint32_t dstB[4];
    #pragma unroll
    for (int i = 0; i < 4; i++) {
        int idx = tid + 256 * i;
        int n = idx >> 3, g = idx & 7;
        srcB[i] = n * 128 + g * 16;
        dstB[i] = 16384 + n * 128 + ((g ^ (n & 7)) << 4);
    }
    const char* xh = (const char*)g_xh;
    const char* wt = (const char*)g_wt;

    // ---- fragment geometry (swizzled, LDS.64) ----
    const int cA = lane & 3;
    const int x2 = 2 * ((lane >> 2) & 7);
    int okk[4];
    #pragma unroll
    for (int kk = 0; kk < 4; kk++) okk[kk] = ((kk * 4 + cA) ^ x2) << 3;
    uint32_t ab[4][2], bbf[4];
    #pragma unroll
    for (int mt = 0; mt < 4; mt++) {
        int r0 = warpM * 64 + mt * 16 + (lane >> 2);
        ab[mt][0] = r0 * 128;
        ab[mt][1] = (r0 + 8) * 128;
    }
    #pragma unroll
    for (int nt = 0; nt < 4; nt++) {
        int n = warpN * 32 + nt * 8 + (lane >> 2);
        bbf[nt] = 16384 + n * 128;
    }

    auto issue = [&](int s) {
        int tap = s >> 2, cc = s & 3;
        int dh = tap / 3, dw = tap - dh * 3;
        uint32_t sb = dbase + (s % NST) * STAGE;
        int aadd = (dh * XHW + dw) * 512 + cc * 128;
        int badd = s * 16384;
        #pragma unroll
        for (int i = 0; i < 4; i++) CP_CG(sb + dstA[i], xh + srcA[i] + aadd);
        #pragma unroll
        for (int i = 0; i < 4; i++) CP_CA(sb + dstB[i], wt + srcB[i] + badd);
        CP_COMMIT();
    };

    // ---- depth-2 pipeline: while computing s, stages s+1 and s+2 are in flight ----
    issue(0);
    issue(1);
    for (int s = 0; s < 36; s++) {
        if (s < 35) { asm volatile("cp.async.wait_group 1;" ::: "memory"); }
        else        { asm volatile("cp.async.wait_group 0;" ::: "memory"); }
        __syncthreads();                  // stage s visible to all; compute(s-1) done everywhere
        if (s < 34) issue(s + 2);         // overwrites stage (s-1)%3 — safe post-barrier

        uint32_t sb = dbase + (s % NST) * STAGE;
        #pragma unroll
        for (int kk = 0; kk < 4; kk++) {
            const int o = okk[kk];
            uint32_t a[4][4];
            #pragma unroll
            for (int mt = 0; mt < 4; mt++) {
                LDS64(a[mt][0], a[mt][2], sb + ab[mt][0] + o);
                LDS64(a[mt][1], a[mt][3], sb + ab[mt][1] + o);
            }
            uint32_t bf[4][2];
            #pragma unroll
            for (int nt = 0; nt < 4; nt++)
                LDS64(bf[nt][0], bf[nt][1], sb + bbf[nt] + o);
            #pragma unroll
            for (int mt = 0; mt < 4; mt++)
                #pragma unroll
                for (int nt = 0; nt < 4; nt++)
                    mma_tf32(acc[mt][nt], a[mt], bf[nt]);
        }
    }

    // ---- epilogue: ti = min(y + 1 - Di[f], 1), NHWC float2 stores (no dead rows) ----
    #pragma unroll
    for (int mt = 0; mt < 4; mt++) {
        #pragma unroll
        for (int half = 0; half < 2; half++) {
            int m = warpM * 64 + mt * 16 + half * 8 + (lane >> 2);
            int p = T * 128 + m;
            int bb = p / PIX_;
            int r  = p - bb * PIX_;
            float* op = out + ((size_t)bb * PIX_ + r) * F_;
            #pragma unroll
            for (int nt = 0; nt < 4; nt++) {
                int f = warpN * 32 + nt * 8 + 2 * (lane & 3);
                float2 vv;
                vv.x = fminf(acc[mt][nt][2 * half + 0] + thr[nt][0], 1.0f);
                vv.y = fminf(acc[mt][nt][2 * half + 1] + thr[nt][1], 1.0f);
                *(float2*)(op + f) = vv;
            }
        }
    }
}

extern "C" void kernel_launch(void* const* d_in, const int* in_sizes, int n_in,
                              void* d_out, int out_size) {
    (void)in_sizes; (void)n_in; (void)out_size;
    const float* x  = (const float*)d_in[0];   // tj  [32,128,56,56]
    const float* Wg = (const float*)d_in[1];   // W   [1152,128]
    const float* Di = (const float*)d_in[2];   // D_i [9,128]
    float* out = (float*)d_out;

    cudaFuncSetAttribute(k_conv_main, cudaFuncAttributeMaxDynamicSharedMemorySize, DYN);

    dim3 gx(XHW, B_);
    k_transpose_x<<<gx, 256>>>(x);
    k_transpose_w<<<(9 * 4 * 128 * 32 + 255) / 256, 256>>>(Wg);

    k_conv_main<<<784, 256, DYN>>>(Di, out);   // 784 tiles of exactly 128 pixels
}

// round 6
// speedup vs baseline: 2.1942x; 1.1754x over previous
#include <cuda_runtime.h>
#include <cstdint>

#define HW_   56
#define C_    128
#define F_    128
#define B_    32
#define PIX_  (HW_*HW_)
#define XHW   58                 // padded spatial
#define STAGE 32768              // A 16KB + B 16KB
#define NST   3
#define DYN   (NST*STAGE + 1024)

// device scratch (static globals = allowed)
__device__ float g_xh[(size_t)B_ * XHW * XHW * C_];  // [b][hp][wp][cperm]
__device__ float g_wt[9 * 4 * 128 * 32];             // [tap][cc][f][kperm]

__device__ __forceinline__ uint32_t smem_u32(const void* p) {
    uint32_t a;
    asm("{ .reg .u64 t; cvta.to.shared.u64 t, %1; cvt.u32.u64 %0, t; }" : "=r"(a) : "l"(p));
    return a;
}
__device__ __forceinline__ void mma_tf32(float d[4], const uint32_t a[4], const uint32_t b[2]) {
    asm volatile(
        "mma.sync.aligned.m16n8k8.row.col.f32.tf32.tf32.f32 "
        "{%0,%1,%2,%3}, {%4,%5,%6,%7}, {%8,%9}, {%0,%1,%2,%3};\n"
        : "+f"(d[0]), "+f"(d[1]), "+f"(d[2]), "+f"(d[3])
        : "r"(a[0]), "r"(a[1]), "r"(a[2]), "r"(a[3]), "r"(b[0]), "r"(b[1]));
}
#define CP_CG(d, s) asm volatile("cp.async.cg.shared.global [%0], [%1], 16;" :: "r"(d), "l"(s))
#define CP_CA(d, s) asm volatile("cp.async.ca.shared.global [%0], [%1], 16;" :: "r"(d), "l"(s))
#define CP_COMMIT() asm volatile("cp.async.commit_group;" ::: "memory")
#define LDS64(r0, r1, a) asm volatile("ld.shared.v2.b32 {%0,%1}, [%2];" : "=r"(r0), "=r"(r1) : "r"(a))

// channel pair-permute within 8-block (k-pair layout for conflict-free LDS.64)
__device__ __host__ __forceinline__ int permC(int c) {
    return (c & ~7) | ((c & 3) << 1) | ((c >> 2) & 1);
}
// inverse: q -> c with permC(c) = q
__device__ __forceinline__ int invPermC(int q) {
    return (q & ~7) | ((q & 7) >> 1) | ((q & 1) << 2);
}

// ---------- prologue 1: x NCHW -> zero-padded NHWC (channel-permuted) ----------
__global__ __launch_bounds__(256) void k_transpose_x(const float* __restrict__ x) {
    __shared__ float s[HW_ * 130];
    const int hp = blockIdx.x, bb = blockIdx.y, tid = threadIdx.x;
    float* dst = g_xh + ((size_t)(bb * XHW + hp) * XHW) * C_;
    if (hp == 0 || hp == XHW - 1) {
        float4 z = make_float4(0.f, 0.f, 0.f, 0.f);
        for (int i = tid; i < XHW * 32; i += 256) ((float4*)dst)[i] = z;
        return;
    }
    const float* src = x + ((size_t)bb * C_) * PIX_ + (hp - 1) * HW_;
    for (int i = tid; i < C_ * HW_; i += 256) {
        int c = i / HW_, w = i - c * HW_;
        s[w * 130 + c] = src[(size_t)c * PIX_ + w];
    }
    __syncthreads();
    // vectorized phase 2: each thread writes one float4 of permuted channels
    for (int o = tid; o < XHW * 32; o += 256) {
        int wp = o >> 5, q4 = (o & 31) << 2;
        float4 v = make_float4(0.f, 0.f, 0.f, 0.f);
        if (wp != 0 && wp != XHW - 1) {
            const float* sr = s + (wp - 1) * 130;
            v.x = sr[invPermC(q4 + 0)];
            v.y = sr[invPermC(q4 + 1)];
            v.z = sr[invPermC(q4 + 2)];
            v.w = sr[invPermC(q4 + 3)];
        }
        ((float4*)dst)[o] = v;
    }
}

// ---------- prologue 2: W[(c*9+tap)][f] -> g_wt[tap][cc][f][kperm] ----------
__global__ __launch_bounds__(256) void k_transpose_w(const float* __restrict__ Wg) {
    int i = blockIdx.x * 256 + threadIdx.x;
    if (i < 9 * 4 * 128 * 32) {
        int t  = i / 16384;
        int r  = i - t * 16384;
        int cc = r >> 12;
        int r2 = r & 4095;
        int n  = r2 >> 5;
        int j  = r2 & 31;
        int c  = cc * 32 + ((j >> 3) << 3) + ((j >> 1) & 3) + ((j & 1) << 2);
        g_wt[i] = Wg[(c * 9 + t) * F_ + n];
    }
}

// ---------- main: 4 warps x (64x64) tiles, depth-2 cp.async pipeline ----------
__global__ __launch_bounds__(128, 2)
void k_conv_main(const float* __restrict__ Di, float* __restrict__ out) {
    extern __shared__ float dynsmem[];
    uint32_t dbase = smem_u32(dynsmem);
    dbase = (dbase + 1023u) & ~1023u;

    const int tid   = threadIdx.x;
    const int lane  = tid & 31;
    const int warp  = tid >> 5;
    const int warpM = warp >> 1;   // 0..1 -> 64 rows
    const int warpN = warp & 1;    // 0..1 -> 64 cols
    const int T     = blockIdx.x;  // pixels [T*128, T*128+128)

    float thr[8][2];
    #pragma unroll
    for (int nt = 0; nt < 8; nt++) {
        int f = warpN * 64 + nt * 8 + 2 * (lane & 3);
        thr[nt][0] = 1.0f - Di[f];
        thr[nt][1] = 1.0f - Di[f + 1];
    }

    float acc[4][8][4];
    #pragma unroll
    for (int mt = 0; mt < 4; mt++)
        #pragma unroll
        for (int nt = 0; nt < 8; nt++)
            #pragma unroll
            for (int r = 0; r < 4; r++) acc[mt][nt][r] = 0.0f;

    // ---- cp.async tables: 8 A + 8 B 16B-copies per thread (128 thr) ----
    int srcA[8];
    #pragma unroll
    for (int i = 0; i < 8; i++) {
        int idx = tid + 128 * i;        // 0..1023
        int m = idx >> 3, g = idx & 7;
        int p = T * 128 + m;
        int bb = p / PIX_;
        int r  = p - bb * PIX_;
        int h  = r / HW_;
        int w  = r - h * HW_;
        srcA[i] = ((bb * XHW + h) * XHW + w) * 512 + g * 16;
    }
    const char* xh = (const char*)g_xh;
    const char* wt = (const char*)g_wt;

    // fragment geometry (swizzled LDS.64)
    const int cA = lane & 3;
    const int x2 = 2 * ((lane >> 2) & 7);
    int okk[4];
    #pragma unroll
    for (int kk = 0; kk < 4; kk++) okk[kk] = ((kk * 4 + cA) ^ x2) << 3;
    uint32_t ab[4][2], bbf[8];
    #pragma unroll
    for (int mt = 0; mt < 4; mt++) {
        int r0 = warpM * 64 + mt * 16 + (lane >> 2);
        ab[mt][0] = r0 * 128;
        ab[mt][1] = (r0 + 8) * 128;
    }
    #pragma unroll
    for (int nt = 0; nt < 8; nt++) {
        int n = warpN * 64 + nt * 8 + (lane >> 2);
        bbf[nt] = 16384 + n * 128;
    }

    auto issue = [&](int s) {
        int tap = s >> 2, cc = s & 3;
        int dh = tap / 3, dw = tap - dh * 3;
        uint32_t sb = dbase + (s % NST) * STAGE;
        int aadd = (dh * XHW + dw) * 512 + cc * 128;
        int badd = s * 16384;
        #pragma unroll
        for (int i = 0; i < 8; i++) {
            int idx = tid + 128 * i;
            int m = idx >> 3, g = idx & 7;
            CP_CG(sb + m * 128 + ((g ^ (m & 7)) << 4), xh + srcA[i] + aadd);
        }
        #pragma unroll
        for (int i = 0; i < 8; i++) {
            int idx = tid + 128 * i;
            int n = idx >> 3, g = idx & 7;
            CP_CA(sb + 16384 + n * 128 + ((g ^ (n & 7)) << 4), wt + idx * 16 + badd);
        }
        CP_COMMIT();
    };

    // ---- depth-2 pipeline ----
    issue(0);
    issue(1);
    for (int s = 0; s < 36; s++) {
        if (s < 35) { asm volatile("cp.async.wait_group 1;" ::: "memory"); }
        else        { asm volatile("cp.async.wait_group 0;" ::: "memory"); }
        __syncthreads();
        if (s < 34) issue(s + 2);

        uint32_t sb = dbase + (s % NST) * STAGE;
        #pragma unroll
        for (int kk = 0; kk < 4; kk++) {
            const int o = okk[kk];
            uint32_t a[4][4];
            #pragma unroll
            for (int mt = 0; mt < 4; mt++) {
                LDS64(a[mt][0], a[mt][2], sb + ab[mt][0] + o);
                LDS64(a[mt][1], a[mt][3], sb + ab[mt][1] + o);
            }
            uint32_t bf[8][2];
            #pragma unroll
            for (int nt = 0; nt < 8; nt++)
                LDS64(bf[nt][0], bf[nt][1], sb + bbf[nt] + o);
            #pragma unroll
            for (int mt = 0; mt < 4; mt++)
                #pragma unroll
                for (int nt = 0; nt < 8; nt++)
                    mma_tf32(acc[mt][nt], a[mt], bf[nt]);
        }
    }

    // ---- epilogue: ti = min(y + 1 - Di[f], 1), NHWC float2 stores ----
    #pragma unroll
    for (int mt = 0; mt < 4; mt++) {
        #pragma unroll
        for (int half = 0; half < 2; half++) {
            int m = warpM * 64 + mt * 16 + half * 8 + (lane >> 2);
            int p = T * 128 + m;
            int bb = p / PIX_;
            int r  = p - bb * PIX_;
            float* op = out + ((size_t)bb * PIX_ + r) * F_;
            #pragma unroll
            for (int nt = 0; nt < 8; nt++) {
                int f = warpN * 64 + nt * 8 + 2 * (lane & 3);
                float2 vv;
                vv.x = fminf(acc[mt][nt][2 * half + 0] + thr[nt][0], 1.0f);
                vv.y = fminf(acc[mt][nt][2 * half + 1] + thr[nt][1], 1.0f);
                *(float2*)(op + f) = vv;
            }
        }
    }
}

extern "C" void kernel_launch(void* const* d_in, const int* in_sizes, int n_in,
                              void* d_out, int out_size) {
    (void)in_sizes; (void)n_in; (void)out_size;
    const float* x  = (const float*)d_in[0];
    const float* Wg = (const float*)d_in[1];
    const float* Di = (const float*)d_in[2];
    float* out = (float*)d_out;

    cudaFuncSetAttribute(k_conv_main, cudaFuncAttributeMaxDynamicSharedMemorySize, DYN);

    dim3 gx(XHW, B_);
    k_transpose_x<<<gx, 256>>>(x);
    k_transpose_w<<<(9 * 4 * 128 * 32 + 255) / 256, 256>>>(Wg);

    k_conv_main<<<784, 128, DYN>>>(Di, out);
}

// round 8
// speedup vs baseline: 2.2097x; 1.0071x over previous
#include <cuda_runtime.h>
#include <cstdint>

#define HW_   56
#define C_    128
#define F_    128
#define B_    32
#define PIX_  (HW_*HW_)
#define XHW   58                 // padded spatial
#define STAGE 32768              // A 16KB + B 16KB
#define NST   3
#define DYN   (NST*STAGE + 1024)

// device scratch (static globals = allowed)
__device__ float g_xh[(size_t)B_ * XHW * XHW * C_];  // [b][hp][wp][cperm]
__device__ float g_wt[9 * 4 * 128 * 32];             // [tap][cc][f][kperm]

__device__ __forceinline__ uint32_t smem_u32(const void* p) {
    uint32_t a;
    asm("{ .reg .u64 t; cvta.to.shared.u64 t, %1; cvt.u32.u64 %0, t; }" : "=r"(a) : "l"(p));
    return a;
}
__device__ __forceinline__ void mma_tf32(float d[4], const uint32_t a[4], const uint32_t b[2]) {
    asm volatile(
        "mma.sync.aligned.m16n8k8.row.col.f32.tf32.tf32.f32 "
        "{%0,%1,%2,%3}, {%4,%5,%6,%7}, {%8,%9}, {%0,%1,%2,%3};\n"
        : "+f"(d[0]), "+f"(d[1]), "+f"(d[2]), "+f"(d[3])
        : "r"(a[0]), "r"(a[1]), "r"(a[2]), "r"(a[3]), "r"(b[0]), "r"(b[1]));
}
#define CP_CG(d, s) asm volatile("cp.async.cg.shared.global [%0], [%1], 16;" :: "r"(d), "l"(s))
#define CP_CA(d, s) asm volatile("cp.async.ca.shared.global [%0], [%1], 16;" :: "r"(d), "l"(s))
#define CP_COMMIT() asm volatile("cp.async.commit_group;" ::: "memory")
#define LDS64(r0, r1, a) asm volatile("ld.shared.v2.b32 {%0,%1}, [%2];" : "=r"(r0), "=r"(r1) : "r"(a))

// channel pair-permute within 8-block (k-pair layout for conflict-free LDS.64)
__device__ __host__ __forceinline__ int permC(int c) {
    return (c & ~7) | ((c & 3) << 1) | ((c >> 2) & 1);
}
// inverse: q -> c with permC(c) = q
__device__ __forceinline__ int invPermC(int q) {
    return (q & ~7) | ((q & 7) >> 1) | ((q & 1) << 2);
}

// ---------- prologue 1: x NCHW -> zero-padded NHWC (channel-permuted) ----------
__global__ __launch_bounds__(256) void k_transpose_x(const float* __restrict__ x) {
    __shared__ float s[HW_ * 130];
    const int hp = blockIdx.x, bb = blockIdx.y, tid = threadIdx.x;
    float* dst = g_xh + ((size_t)(bb * XHW + hp) * XHW) * C_;
    if (hp == 0 || hp == XHW - 1) {
        float4 z = make_float4(0.f, 0.f, 0.f, 0.f);
        for (int i = tid; i < XHW * 32; i += 256) ((float4*)dst)[i] = z;
        return;
    }
    const float* src = x + ((size_t)bb * C_) * PIX_ + (hp - 1) * HW_;
    for (int i = tid; i < C_ * HW_; i += 256) {
        int c = i / HW_, w = i - c * HW_;
        s[w * 130 + c] = src[(size_t)c * PIX_ + w];
    }
    __syncthreads();
    for (int o = tid; o < XHW * 32; o += 256) {
        int wp = o >> 5, q4 = (o & 31) << 2;
        float4 v = make_float4(0.f, 0.f, 0.f, 0.f);
        if (wp != 0 && wp != XHW - 1) {
            const float* sr = s + (wp - 1) * 130;
            v.x = sr[invPermC(q4 + 0)];
            v.y = sr[invPermC(q4 + 1)];
            v.z = sr[invPermC(q4 + 2)];
            v.w = sr[invPermC(q4 + 3)];
        }
        ((float4*)dst)[o] = v;
    }
}

// ---------- prologue 2: W[(c*9+tap)][f] -> g_wt[tap][cc][f][kperm] ----------
__global__ __launch_bounds__(256) void k_transpose_w(const float* __restrict__ Wg) {
    int i = blockIdx.x * 256 + threadIdx.x;
    if (i < 9 * 4 * 128 * 32) {
        int t  = i / 16384;
        int r  = i - t * 16384;
        int cc = r >> 12;
        int r2 = r & 4095;
        int n  = r2 >> 5;
        int j  = r2 & 31;
        int c  = cc * 32 + ((j >> 3) << 3) + ((j >> 1) & 3) + ((j & 1) << 2);
        g_wt[i] = Wg[(c * 9 + t) * F_ + n];
    }
}

// ---------- main: 4 warps x (64x64), reg-double-buffered fragments ----------
__global__ __launch_bounds__(128, 2)
void k_conv_main(const float* __restrict__ Di, float* __restrict__ out) {
    extern __shared__ float dynsmem[];
    uint32_t dbase = smem_u32(dynsmem);
    dbase = (dbase + 1023u) & ~1023u;

    const int tid   = threadIdx.x;
    const int lane  = tid & 31;
    const int warp  = tid >> 5;
    const int warpM = warp >> 1;   // 0..1 -> 64 rows
    const int warpN = warp & 1;    // 0..1 -> 64 cols
    const int T     = blockIdx.x;  // pixels [T*128, T*128+128)

    float thr[8][2];
    #pragma unroll
    for (int nt = 0; nt < 8; nt++) {
        int f = warpN * 64 + nt * 8 + 2 * (lane & 3);
        thr[nt][0] = 1.0f - Di[f];
        thr[nt][1] = 1.0f - Di[f + 1];
    }

    float acc[4][8][4];
    #pragma unroll
    for (int mt = 0; mt < 4; mt++)
        #pragma unroll
        for (int nt = 0; nt < 8; nt++)
            #pragma unroll
            for (int r = 0; r < 4; r++) acc[mt][nt][r] = 0.0f;

    // ---- cp.async source table: 8 A-copies per thread ----
    int srcA[8];
    #pragma unroll
    for (int i = 0; i < 8; i++) {
        int idx = tid + 128 * i;        // 0..1023
        int m = idx >> 3;
        int p = T * 128 + m;
        int bb = p / PIX_;
        int r  = p - bb * PIX_;
        int h  = r / HW_;
        int w  = r - h * HW_;
        srcA[i] = ((bb * XHW + h) * XHW + w) * 512 + (idx & 7) * 16;
    }
    const char* xh = (const char*)g_xh;
    const char* wt = (const char*)g_wt;

    // fragment geometry (swizzled LDS.64)
    const int cA = lane & 3;
    const int x2 = 2 * ((lane >> 2) & 7);
    int okk[4];
    #pragma unroll
    for (int kk = 0; kk < 4; kk++) okk[kk] = ((kk * 4 + cA) ^ x2) << 3;
    uint32_t ab[4][2], bbf[8];
    #pragma unroll
    for (int mt = 0; mt < 4; mt++) {
        int r0 = warpM * 64 + mt * 16 + (lane >> 2);
        ab[mt][0] = r0 * 128;
        ab[mt][1] = (r0 + 8) * 128;
    }
    #pragma unroll
    for (int nt = 0; nt < 8; nt++) {
        int n = warpN * 64 + nt * 8 + (lane >> 2);
        bbf[nt] = 16384 + n * 128;
    }

    // per-thread cp.async dst offsets (within a stage)
    uint32_t dstA[8], dstB[8];
    #pragma unroll
    for (int i = 0; i < 8; i++) {
        int idx = tid + 128 * i;
        int m = idx >> 3, g = idx & 7;
        dstA[i] = m * 128 + ((g ^ (m & 7)) << 4);
        dstB[i] = 16384 + m * 128 + ((g ^ (m & 7)) << 4);   // n == m layout-wise
    }

    auto issue = [&](int s, uint32_t sb) {
        int tap = s >> 2, cc = s & 3;
        int dh = tap / 3, dw = tap - dh * 3;
        int aadd = (dh * XHW + dw) * 512 + cc * 128;
        long badd = (long)s * 16384;
        #pragma unroll
        for (int i = 0; i < 8; i++) CP_CG(sb + dstA[i], xh + srcA[i] + aadd);
        #pragma unroll
        for (int i = 0; i < 8; i++) CP_CA(sb + dstB[i], wt + (long)(tid + 128 * i) * 16 + badd);
        CP_COMMIT();
    };

    // double-buffered fragment registers
    uint32_t a[2][4][4];
    uint32_t bf[2][8][2];

    auto load_frags = [&](uint32_t sb, int kk, int buf) {
        const int o = okk[kk];
        #pragma unroll
        for (int mt = 0; mt < 4; mt++) {
            LDS64(a[buf][mt][0], a[buf][mt][2], sb + ab[mt][0] + o);
            LDS64(a[buf][mt][1], a[buf][mt][3], sb + ab[mt][1] + o);
        }
        #pragma unroll
        for (int nt = 0; nt < 8; nt++)
            LDS64(bf[buf][nt][0], bf[buf][nt][1], sb + bbf[nt] + o);
    };

    // ---- depth-2 cp.async pipeline + in-step register prefetch ----
    uint32_t sb0 = dbase, sb1 = dbase + STAGE, sb2 = dbase + 2 * STAGE;
    issue(0, sb0);
    issue(1, sb1);
    #pragma unroll 1
    for (int s = 0; s < 36; s++) {
        if (s < 35) { asm volatile("cp.async.wait_group 1;" ::: "memory"); }
        else        { asm volatile("cp.async.wait_group 0;" ::: "memory"); }
        __syncthreads();
        if (s < 34) issue(s + 2, sb2);

        load_frags(sb0, 0, 0);
        #pragma unroll
        for (int kk = 0; kk < 4; kk++) {
            int cur = kk & 1;
            if (kk < 3) load_frags(sb0, kk + 1, cur ^ 1);
            #pragma unroll
            for (int mt = 0; mt < 4; mt++)
                #pragma unroll
                for (int nt = 0; nt < 8; nt++)
                    mma_tf32(acc[mt][nt], a[cur][mt], bf[cur][nt]);
        }
        uint32_t t0 = sb0; sb0 = sb1; sb1 = sb2; sb2 = t0;   // rotate stages
    }

    // ---- epilogue: ti = min(y + 1 - Di[f], 1), NHWC float2 stores ----
    #pragma unroll
    for (int mt = 0; mt < 4; mt++) {
        #pragma unroll
        for (int half = 0; half < 2; half++) {
            int m = warpM * 64 + mt * 16 + half * 8 + (lane >> 2);
            int p = T * 128 + m;
            int bb = p / PIX_;
            int r  = p - bb * PIX_;
            float* op = out + ((size_t)bb * PIX_ + r) * F_;
            #pragma unroll
            for (int nt = 0; nt < 8; nt++) {
                int f = warpN * 64 + nt * 8 + 2 * (lane & 3);
                float2 vv;
                vv.x = fminf(acc[mt][nt][2 * half + 0] + thr[nt][0], 1.0f);
                vv.y = fminf(acc[mt][nt][2 * half + 1] + thr[nt][1], 1.0f);
                *(float2*)(op + f) = vv;
            }
        }
    }
}

extern "C" void kernel_launch(void* const* d_in, const int* in_sizes, int n_in,
                              void* d_out, int out_size) {
    (void)in_sizes; (void)n_in; (void)out_size;
    const float* x  = (const float*)d_in[0];
    const float* Wg = (const float*)d_in[1];
    const float* Di = (const float*)d_in[2];
    float* out = (float*)d_out;

    cudaFuncSetAttribute(k_conv_main, cudaFuncAttributeMaxDynamicSharedMemorySize, DYN);

    dim3 gx(XHW, B_);
    k_transpose_x<<<gx, 256>>>(x);
    k_transpose_w<<<(9 * 4 * 128 * 32 + 255) / 256, 256>>>(Wg);

    k_conv_main<<<784, 128, DYN>>>(Di, out);
}